// round 13
// baseline (speedup 1.0000x reference)
#include <cuda_runtime.h>
#include <cuda_fp16.h>
#include <cstdint>

#define BB 8
#define NC 2048
#define YD 8
#define GR 128
#define MM (GR*GR)
#define KC 64            // K per chunk (64 halfs = 128B rows)
#define KSPL 4           // K split across CTAs
#define KPER (NC/KSPL)   // 512
#define NCHK (KPER/KC)   // 8 chunks per CTA
#define STAGE 24576      // A(16KB) + B(8KB) per pipeline stage
#define NSTAGE 3
#define GG 320           // 8b * 5yp * 2ixh * 4ks

// ---- device scratch ----
__device__ __half g_w[2][BB][GR][NC];        // [axis(0=x,1=y)][b][row][n]
__device__ __half g_yl[BB][YD + 1][NC];      // [b][ych][n], ych 0 -> 1.0
__device__ float  g_s[KSPL][BB][YD + 1][MM]; // partial GEMM outputs

// ---- helpers ----
__device__ __forceinline__ float ex2f(float x) {
    float y; asm("ex2.approx.f32 %0, %1;" : "=f"(y) : "f"(x)); return y;
}
__device__ __forceinline__ float rcpf(float x) {
    float y; asm("rcp.approx.f32 %0, %1;" : "=f"(y) : "f"(x)); return y;
}
__device__ __forceinline__ uint32_t s2u(const void* p) {
    uint32_t a;
    asm("{ .reg .u64 t; cvta.to.shared.u64 t, %1; cvt.u32.u64 %0, t; }" : "=r"(a) : "l"(p));
    return a;
}
__device__ __forceinline__ uint32_t hmul2u(uint32_t a, uint32_t b) {
    __half2 r = __hmul2(*(__half2*)&a, *(__half2*)&b);
    return *(uint32_t*)&r;
}
__device__ __forceinline__ uint32_t pkh2(float hi, float lo) {
    uint32_t r;
    asm("cvt.rn.f16x2.f32 %0, %1, %2;" : "=r"(r) : "f"(hi), "f"(lo));
    return r;
}
__device__ __forceinline__ void cpasync16(uint32_t dst, const void* src) {
    asm volatile("cp.async.cg.shared.global [%0], [%1], 16;" :: "r"(dst), "l"(src) : "memory");
}
#define CP_COMMIT() asm volatile("cp.async.commit_group;" ::: "memory")
#define CP_WAIT1()  asm volatile("cp.async.wait_group 1;" ::: "memory")
#define CP_WAIT0()  asm volatile("cp.async.wait_group 0;" ::: "memory")

__device__ __forceinline__ void ldm4(uint32_t* r, uint32_t addr) {
    asm volatile("ldmatrix.sync.aligned.m8n8.x4.shared.b16 {%0,%1,%2,%3}, [%4];"
        : "=r"(r[0]), "=r"(r[1]), "=r"(r[2]), "=r"(r[3]) : "r"(addr));
}
__device__ __forceinline__ void mma16816(float* d, const uint32_t* a, const uint32_t* bf) {
    asm volatile("mma.sync.aligned.m16n8k16.row.col.f32.f16.f16.f32 "
        "{%0,%1,%2,%3}, {%4,%5,%6,%7}, {%8,%9}, {%0,%1,%2,%3};"
        : "+f"(d[0]), "+f"(d[1]), "+f"(d[2]), "+f"(d[3])
        : "r"(a[0]), "r"(a[1]), "r"(a[2]), "r"(a[3]), "r"(bf[0]), "r"(bf[1]));
}

// =====================  precompute (R7 winner, grid 400, 6.3us)  =====================
__global__ void __launch_bounds__(256)
pre_all(const float* __restrict__ xc, const float* __restrict__ yc,
        const float* __restrict__ gp, const float* __restrict__ sigma)
{
    const int bx = blockIdx.x;
    if (bx < 256) {
        const int axis = bx >> 7;
        const int b    = (bx >> 4) & 7;
        const int rg   = (bx >> 1) & 7;
        const int ns   = bx & 1;
        const float sg = sigma[0];
        const float cc = -0.5f * 1.4426950408889634f / (sg * sg);

        __shared__ float sg_g[16], sg_c2[16];
        if (threadIdx.x < 16) {
            const int row = rg * 16 + threadIdx.x;
            const float g = (axis == 0) ? gp[2 * row] : gp[2 * (row * GR) + 1];
            sg_g[threadIdx.x]  = g;
            sg_c2[threadIdx.x] = cc * g * g;
        }
        __syncthreads();

        const int n0 = ns * 1024 + threadIdx.x * 4;
        const float4 xv01 = ((const float4*)xc)[((size_t)b * NC + n0) >> 1];
        const float4 xv23 = ((const float4*)xc)[(((size_t)b * NC + n0) >> 1) + 1];
        const float c0 = axis ? xv01.y : xv01.x;
        const float c1 = axis ? xv01.w : xv01.z;
        const float c2v = axis ? xv23.y : xv23.x;
        const float c3 = axis ? xv23.w : xv23.z;
        const float a00 = cc * c0 * c0,   a10 = -2.0f * cc * c0;
        const float a01 = cc * c1 * c1,   a11 = -2.0f * cc * c1;
        const float a02 = cc * c2v * c2v, a12 = -2.0f * cc * c2v;
        const float a03 = cc * c3 * c3,   a13 = -2.0f * cc * c3;
#pragma unroll
        for (int rr = 0; rr < 16; rr++) {
            const float g = sg_g[rr], k2 = sg_c2[rr];
            const float e0 = ex2f(fmaf(a10, g, a00 + k2));
            const float e1 = ex2f(fmaf(a11, g, a01 + k2));
            const float e2 = ex2f(fmaf(a12, g, a02 + k2));
            const float e3 = ex2f(fmaf(a13, g, a03 + k2));
            uint2 v; v.x = pkh2(e1, e0); v.y = pkh2(e3, e2);
            *(uint2*)&g_w[axis][b][rg * 16 + rr][n0] = v;
        }
    } else {
        const int r   = bx - 256;        // 144 = 8 * 9 * 2
        const int b   = r / 18;
        const int rr  = r % 18;
        const int ych = rr >> 1;
        const int ns  = rr & 1;
        const int n0  = ns * 1024 + threadIdx.x * 4;
        uint2 v;
        if (ych == 0) {
            v.x = 0x3C003C00u; v.y = 0x3C003C00u;
        } else {
            const float* yb = yc + ((size_t)b * NC + n0) * YD + (ych - 1);
            v.x = pkh2(yb[8],  yb[0]);
            v.y = pkh2(yb[24], yb[16]);
        }
        *(uint2*)&g_yl[b][ych][n0] = v;
    }
}

// =====================  GEMM v2: 128m x 64n x 2ych, register-lean  =====================
// CTA = (b, yp, ixh, ks). Channels {2yp, 2yp+1}; yp=4 computes only channel 8.
__global__ void __launch_bounds__(256, 2)
rbf_gemm()
{
    extern __shared__ __align__(1024) char smem[];
    const uint32_t sb = s2u(smem);

    const int tid  = threadIdx.x;
    const int lane = tid & 31;

    const int bx  = blockIdx.x;      // 320 = 8 * 5 * 2 * 4
    const int b   = bx / 40;
    const int r   = bx % 40;
    const int yp  = r >> 3;          // 0..4
    const int ixh = (r >> 2) & 1;
    const int ks  = r & 3;
    const int ych0 = yp * 2;
    const bool dual = (yp < 4);

    // ---- cp.async staging: base + affine offsets ----
    // thread covers A rows {row0, row0+32, row0+64, row0+96}, B rows {row0, row0+32}
    const uint32_t off0 = (uint32_t)(tid >> 3) * 128u + (uint32_t)(tid & 7) * 16u;
    const uint32_t sw0  = off0 ^ ((off0 >> 3) & 0x70);
    const char* aBase = (const char*)&g_w[1][b][tid >> 3][ks * KPER + (tid & 7) * 8];
    const char* bBase = (const char*)&g_w[0][b][ixh * 64 + (tid >> 3)][ks * KPER + (tid & 7) * 8];

    auto cp_stage = [&](int c, int st) {
        const uint32_t dst = sb + (uint32_t)st * STAGE + sw0;
        const int boff = c * 128;    // 64 halfs per chunk
#pragma unroll
        for (int rr = 0; rr < 4; rr++)
            cpasync16(dst + (uint32_t)rr * 4096u, aBase + boff + rr * (32 * NC * 2));
#pragma unroll
        for (int rr = 0; rr < 2; rr++)
            cpasync16(dst + 16384u + (uint32_t)rr * 4096u, bBase + boff + rr * (32 * NC * 2));
    };

    // ---- ldmatrix addressing: single xor, affine row offsets ----
    const uint32_t xo   = (uint32_t)(lane & 7) << 4;
    const uint32_t roA0 = ((uint32_t)(((tid >> 6) & 3) * 32 + (lane & 15))) * 128u;  // warp_m rows
    const uint32_t subA = ((lane >> 4) & 1) * 16u;
    const uint32_t roB0 = 16384u
        + ((uint32_t)(((tid >> 5) & 1) * 32 + ((lane >> 4) & 1) * 8 + (lane & 7))) * 128u; // warp_n rows
    const uint32_t subB = ((lane >> 3) & 1) * 16u;

    const __half* __restrict__ ylp = &g_yl[b][ych0][ks * KPER] + (lane & 3) * 2;
    const uint32_t ylOff = dual ? NC : 0u;   // second channel offset (halfs)

    float acc[2][2][4][4];
#pragma unroll
    for (int e = 0; e < 2; e++)
#pragma unroll
        for (int f = 0; f < 2; f++)
#pragma unroll
            for (int g = 0; g < 4; g++)
#pragma unroll
                for (int q = 0; q < 4; q++) acc[e][f][g][q] = 0.0f;

    // ---- 3-stage pipeline prologue ----
    cp_stage(0, 0); CP_COMMIT();
    cp_stage(1, 1); CP_COMMIT();

    for (int k = 0; k < NCHK; k++) {
        if (k == NCHK - 1) { CP_WAIT0(); } else { CP_WAIT1(); }
        __syncthreads();                       // chunk k visible; stage (k+2)%3 free
        if (k + 2 < NCHK) { cp_stage(k + 2, (k + 2) % 3); CP_COMMIT(); }

        const uint32_t stb = sb + (uint32_t)(k % 3) * STAGE;
#pragma unroll
        for (int s = 0; s < 4; s++) {
            const uint32_t qA = ((uint32_t)(s * 32) + subA) ^ xo;
            const uint32_t qB = ((uint32_t)(s * 32) + subB) ^ xo;

            // shared wy fragments (ych-independent)
            uint32_t wy[2][4];
#pragma unroll
            for (int f = 0; f < 2; f++)
                ldm4(wy[f], stb + roA0 + (uint32_t)f * 2048u + qA);

            // B fragments (n32 per warp -> 4 n8 groups)
            uint32_t bfr[4][2];
#pragma unroll
            for (int gp2 = 0; gp2 < 2; gp2++) {
                uint32_t t[4];
                ldm4(t, stb + roB0 + (uint32_t)gp2 * 2048u + qB);
                bfr[gp2 * 2 + 0][0] = t[0]; bfr[gp2 * 2 + 0][1] = t[1];
                bfr[gp2 * 2 + 1][0] = t[2]; bfr[gp2 * 2 + 1][1] = t[3];
            }

            const __half* ylk = ylp + (uint32_t)(k * KC + s * 16);

            // ych0
            {
                const uint32_t yA = *(const uint32_t*)(ylk);
                const uint32_t yB = *(const uint32_t*)(ylk + 8);
#pragma unroll
                for (int f = 0; f < 2; f++) {
                    uint32_t afr[4];
                    afr[0] = hmul2u(wy[f][0], yA);
                    afr[1] = hmul2u(wy[f][1], yA);
                    afr[2] = hmul2u(wy[f][2], yB);
                    afr[3] = hmul2u(wy[f][3], yB);
#pragma unroll
                    for (int g = 0; g < 4; g++)
                        mma16816(acc[0][f][g], afr, bfr[g]);
                }
            }
            // ych1 (uniform per-CTA branch; skipped for the singleton)
            if (dual) {
                const uint32_t yA = *(const uint32_t*)(ylk + ylOff);
                const uint32_t yB = *(const uint32_t*)(ylk + ylOff + 8);
#pragma unroll
                for (int f = 0; f < 2; f++) {
                    uint32_t afr[4];
                    afr[0] = hmul2u(wy[f][0], yA);
                    afr[1] = hmul2u(wy[f][1], yA);
                    afr[2] = hmul2u(wy[f][2], yB);
                    afr[3] = hmul2u(wy[f][3], yB);
#pragma unroll
                    for (int g = 0; g < 4; g++)
                        mma16816(acc[1][f][g], afr, bfr[g]);
                }
            }
        }
    }

    // ---- epilogue: partial tiles -> g_s[ks] ----
    const int warp_m = (tid >> 6) & 3;
    const int warp_n = (tid >> 5) & 1;
    const int cb  = ixh * 64 + warp_n * 32 + (lane & 3) * 2;
    const int rlo = lane >> 2;
    float* dst0 = &g_s[ks][b][ych0][0];
#pragma unroll
    for (int e = 0; e < 2; e++) {
        if (e == 1 && !dual) break;
        float* dst = dst0 + (size_t)e * MM;
#pragma unroll
        for (int f = 0; f < 2; f++) {
            const int rowb = warp_m * 32 + f * 16 + rlo;
#pragma unroll
            for (int g = 0; g < 4; g++) {
                const int cc2 = cb + g * 8;
                *(float2*)(dst + (size_t)rowb * GR + cc2)       = make_float2(acc[e][f][g][0], acc[e][f][g][1]);
                *(float2*)(dst + (size_t)(rowb + 8) * GR + cc2) = make_float2(acc[e][f][g][2], acc[e][f][g][3]);
            }
        }
    }
}

// =====================  combine / normalize (R7 winner)  =====================
__global__ void __launch_bounds__(256)
rbf_comb(float* __restrict__ out)
{
    const int bx = blockIdx.x;
    const int b  = bx / 144;
    const int rr = bx % 144;
    const int ch = rr >> 4;
    const int m4 = (((rr & 15) << 8) + threadIdx.x) * 4;

    float4 dv = *(const float4*)&g_s[0][b][0][m4];
#pragma unroll
    for (int p = 1; p < KSPL; p++) {
        const float4 d = *(const float4*)&g_s[p][b][0][m4];
        dv.x += d.x; dv.y += d.y; dv.z += d.z; dv.w += d.w;
    }

    float* op = out + ((size_t)b * (YD + 1) + ch) * MM + m4;
    if (ch == 0) {
        *(float4*)op = dv;
        return;
    }
    float4 a = *(const float4*)&g_s[0][b][ch][m4];
#pragma unroll
    for (int p = 1; p < KSPL; p++) {
        const float4 d = *(const float4*)&g_s[p][b][ch][m4];
        a.x += d.x; a.y += d.y; a.z += d.z; a.w += d.w;
    }
    a.x *= rcpf(dv.x + 1e-5f);
    a.y *= rcpf(dv.y + 1e-5f);
    a.z *= rcpf(dv.z + 1e-5f);
    a.w *= rcpf(dv.w + 1e-5f);
    *(float4*)op = a;
}

extern "C" void kernel_launch(void* const* d_in, const int* in_sizes, int n_in,
                              void* d_out, int out_size)
{
    const float* xc    = (const float*)d_in[0];  // (8, 2048, 2)
    const float* yc    = (const float*)d_in[1];  // (8, 2048, 8)
    const float* gp    = (const float*)d_in[2];  // (1, 16384, 2)
    const float* sigma = (const float*)d_in[3];  // scalar
    float* out = (float*)d_out;                  // (8, 9, 128, 128)

    cudaFuncSetAttribute(rbf_gemm, cudaFuncAttributeMaxDynamicSharedMemorySize,
                         NSTAGE * STAGE);
    pre_all<<<400, 256>>>(xc, yc, gp, sigma);
    rbf_gemm<<<GG, 256, NSTAGE * STAGE>>>();
    rbf_comb<<<1152, 256>>>(out);
}

// round 14
// speedup vs baseline: 1.3601x; 1.3601x over previous
#include <cuda_runtime.h>
#include <cuda_fp16.h>
#include <cstdint>

#define BB 8
#define NC 2048
#define YD 8
#define GR 128
#define MM (GR*GR)
#define KC 64            // K per chunk (64 halfs = 128B rows)
#define KSPL 4           // K split across CTAs
#define KPER (NC/KSPL)   // 512
#define NCHK (KPER/KC)   // 8 chunks per CTA
#define STAGE 32768      // A(16KB) + B(16KB) per pipeline stage
#define NSTAGE 3

// ---- device scratch ----
__device__ __half g_w[2][BB][GR][NC];        // [axis(0=x,1=y)][b][row][n]
__device__ __half g_yl[BB][YD + 1][NC];      // [b][ych][n], ych 0 -> 1.0
__device__ float  g_s[KSPL][BB][YD + 1][MM]; // partial GEMM outputs

// ---- helpers ----
__device__ __forceinline__ float ex2f(float x) {
    float y; asm("ex2.approx.f32 %0, %1;" : "=f"(y) : "f"(x)); return y;
}
__device__ __forceinline__ float rcpf(float x) {
    float y; asm("rcp.approx.f32 %0, %1;" : "=f"(y) : "f"(x)); return y;
}
__device__ __forceinline__ uint32_t s2u(const void* p) {
    uint32_t a;
    asm("{ .reg .u64 t; cvta.to.shared.u64 t, %1; cvt.u32.u64 %0, t; }" : "=r"(a) : "l"(p));
    return a;
}
__device__ __forceinline__ uint32_t hmul2u(uint32_t a, uint32_t b) {
    __half2 r = __hmul2(*(__half2*)&a, *(__half2*)&b);
    return *(uint32_t*)&r;
}
__device__ __forceinline__ uint32_t pkh2(float hi, float lo) {
    uint32_t r;
    asm("cvt.rn.f16x2.f32 %0, %1, %2;" : "=r"(r) : "f"(hi), "f"(lo));
    return r;
}
__device__ __forceinline__ void cpasync16(uint32_t dst, const void* src) {
    asm volatile("cp.async.cg.shared.global [%0], [%1], 16;" :: "r"(dst), "l"(src) : "memory");
}
#define CP_COMMIT() asm volatile("cp.async.commit_group;" ::: "memory")
#define CP_WAIT1()  asm volatile("cp.async.wait_group 1;" ::: "memory")
#define CP_WAIT0()  asm volatile("cp.async.wait_group 0;" ::: "memory")

__device__ __forceinline__ void ldm4(uint32_t* r, uint32_t addr) {
    asm volatile("ldmatrix.sync.aligned.m8n8.x4.shared.b16 {%0,%1,%2,%3}, [%4];"
        : "=r"(r[0]), "=r"(r[1]), "=r"(r[2]), "=r"(r[3]) : "r"(addr));
}
__device__ __forceinline__ void mma16816(float* d, const uint32_t* a, const uint32_t* bf) {
    asm volatile("mma.sync.aligned.m16n8k16.row.col.f32.f16.f16.f32 "
        "{%0,%1,%2,%3}, {%4,%5,%6,%7}, {%8,%9}, {%0,%1,%2,%3};"
        : "+f"(d[0]), "+f"(d[1]), "+f"(d[2]), "+f"(d[3])
        : "r"(a[0]), "r"(a[1]), "r"(a[2]), "r"(a[3]), "r"(bf[0]), "r"(bf[1]));
}

// =====================  precompute: 8 rows x 8 n per thread, STG.128  =====================
// grid = 400: [0,256) weights: axis(2) x b(8) x rowgroup(16 of 8 rows), full n per CTA
//             [256,400) yl: b(8) x ych(9) x ns(2)
__global__ void __launch_bounds__(256)
pre_all(const float* __restrict__ xc, const float* __restrict__ yc,
        const float* __restrict__ gp, const float* __restrict__ sigma)
{
    const int bx = blockIdx.x;
    if (bx < 256) {
        const int axis = bx >> 7;
        const int b    = (bx >> 4) & 7;
        const int rg   = bx & 15;            // 16 groups of 8 rows
        const float sg = sigma[0];
        const float cc = -0.5f * 1.4426950408889634f / (sg * sg);

        __shared__ float sg_g[8], sg_c2[8];
        if (threadIdx.x < 8) {
            const int row = rg * 8 + threadIdx.x;
            const float g = (axis == 0) ? gp[2 * row] : gp[2 * (row * GR) + 1];
            sg_g[threadIdx.x]  = g;
            sg_c2[threadIdx.x] = cc * g * g;
        }
        __syncthreads();

        const int n0 = threadIdx.x * 8;      // 256 threads x 8 n = 2048
        float a0[8], a1[8];
#pragma unroll
        for (int j = 0; j < 4; j++) {
            const float4 xv = ((const float4*)xc)[((size_t)b * NC + n0) / 2 + j];
            const float cA = axis ? xv.y : xv.x;
            const float cB = axis ? xv.w : xv.z;
            a0[2 * j]     = cc * cA * cA;  a1[2 * j]     = -2.0f * cc * cA;
            a0[2 * j + 1] = cc * cB * cB;  a1[2 * j + 1] = -2.0f * cc * cB;
        }

        __half* wbase = &g_w[axis][b][rg * 8][n0];
#pragma unroll
        for (int rr = 0; rr < 8; rr++) {
            const float g = sg_g[rr], k2 = sg_c2[rr];
            float e[8];
#pragma unroll
            for (int j = 0; j < 8; j++)
                e[j] = ex2f(fmaf(a1[j], g, a0[j] + k2));   // 8 independent MUFU chains
            uint4 v;
            v.x = pkh2(e[1], e[0]);
            v.y = pkh2(e[3], e[2]);
            v.z = pkh2(e[5], e[4]);
            v.w = pkh2(e[7], e[6]);
            *(uint4*)(wbase + (size_t)rr * NC) = v;        // STG.128, coalesced along n
        }
    } else {
        const int r   = bx - 256;        // 144 = 8 * 9 * 2
        const int b   = r / 18;
        const int rr  = r % 18;
        const int ych = rr >> 1;
        const int ns  = rr & 1;
        const int n0  = ns * 1024 + threadIdx.x * 4;
        uint2 v;
        if (ych == 0) {
            v.x = 0x3C003C00u; v.y = 0x3C003C00u;
        } else {
            const float* yb = yc + ((size_t)b * NC + n0) * YD + (ych - 1);
            v.x = pkh2(yb[8],  yb[0]);
            v.y = pkh2(yb[24], yb[16]);
        }
        *(uint2*)&g_yl[b][ych][n0] = v;
    }
#if __CUDA_ARCH__ >= 900
    cudaTriggerProgrammaticLaunchCompletion();
#endif
}

// =====================  main GEMM: 128x128 tile, cp.async 3-stage (R7 winner)  =====================
// CTA = (b, ych, ks). D[iy 0..127][ix 0..127] = sum_{n in Kslice} (yl[n]*wy[n,iy])*wx[n,ix]
__global__ void __launch_bounds__(256, 2)
rbf_gemm()
{
    extern __shared__ __align__(1024) char smem[];
    const uint32_t sb = s2u(smem);

    const int tid  = threadIdx.x;
    const int wid  = tid >> 5;
    const int lane = tid & 31;
    const int warp_m = wid >> 1;     // 0..3 (m32 each)
    const int warp_n = wid & 1;      // 0..1 (n64 each)

    const int bx  = blockIdx.x;      // 288 = 8 * 9 * 4
    const int b   = bx / 36;
    const int r   = bx % 36;
    const int ych = r >> 2;
    const int ks  = r & 3;

    // ---- cp.async staging maps (per thread: 4 A rows + 4 B rows, 16B each) ----
    const int col8 = tid & 7;
    const int row0 = tid >> 3;       // 0..31
    uint32_t sw[4];
#pragma unroll
    for (int rr = 0; rr < 4; rr++) {
        const uint32_t off = (uint32_t)(row0 + 32 * rr) * 128u + (uint32_t)col8 * 16u;
        sw[rr] = off ^ ((off >> 3) & 0x70);
    }
    const char* aR[4];
    const char* bR[4];
#pragma unroll
    for (int rr = 0; rr < 4; rr++) {
        aR[rr] = (const char*)&g_w[1][b][row0 + 32 * rr][ks * KPER + col8 * 8];
        bR[rr] = (const char*)&g_w[0][b][row0 + 32 * rr][ks * KPER + col8 * 8];
    }

    auto cp_stage = [&](int c, int st) {
        const uint32_t base = sb + (uint32_t)st * STAGE;
        const int boff = c * 128;    // 64 halfs per chunk
#pragma unroll
        for (int rr = 0; rr < 4; rr++) cpasync16(base + sw[rr], aR[rr] + boff);
#pragma unroll
        for (int rr = 0; rr < 4; rr++) cpasync16(base + 16384u + sw[rr], bR[rr] + boff);
    };

    // ---- ldmatrix address components (stage-relative) ----
    uint32_t roA[2], xoA[2];
#pragma unroll
    for (int f = 0; f < 2; f++) {
        const uint32_t rA = warp_m * 32 + f * 16 + (lane & 15);
        roA[f] = rA * 128u;
        xoA[f] = (rA & 7) << 4;
    }
    const uint32_t subA = ((lane >> 4) & 1) * 16u;
    uint32_t roB[4], xoB[4];
#pragma unroll
    for (int gp2 = 0; gp2 < 4; gp2++) {
        const uint32_t rB = warp_n * 64 + gp2 * 16 + ((lane >> 4) & 1) * 8 + (lane & 7);
        roB[gp2] = 16384u + rB * 128u;
        xoB[gp2] = (rB & 7) << 4;
    }
    const uint32_t subB = ((lane >> 3) & 1) * 16u;

    const __half* __restrict__ ylp = &g_yl[b][ych][ks * KPER];
    const uint32_t ylo = (lane & 3) * 2;

    float acc[2][8][4];
#pragma unroll
    for (int f = 0; f < 2; f++)
#pragma unroll
        for (int g = 0; g < 8; g++)
#pragma unroll
            for (int e = 0; e < 4; e++) acc[f][g][e] = 0.0f;

#if __CUDA_ARCH__ >= 900
    cudaGridDependencySynchronize();   // wait for pre_all's writes; prologue above overlapped
#endif

    // ---- 3-stage pipeline prologue ----
    cp_stage(0, 0); CP_COMMIT();
    cp_stage(1, 1); CP_COMMIT();

    for (int k = 0; k < NCHK; k++) {
        if (k == NCHK - 1) { CP_WAIT0(); } else { CP_WAIT1(); }
        __syncthreads();                       // chunk k visible; stage (k+2)%3 free
        if (k + 2 < NCHK) { cp_stage(k + 2, (k + 2) % 3); CP_COMMIT(); }

        const uint32_t stb = sb + (uint32_t)(k % 3) * STAGE;
#pragma unroll
        for (int s = 0; s < 4; s++) {
            uint32_t afr[2][4];
#pragma unroll
            for (int f = 0; f < 2; f++)
                ldm4(afr[f], stb + roA[f] + (((uint32_t)(s * 32) + subA) ^ xoA[f]));

            // yl multiply on A fragments (regs 0,1 = k-lo pair; 2,3 = k-hi pair)
            const uint32_t koff = (uint32_t)(k * KC + s * 16) + ylo;
            const uint32_t ylA = *(const uint32_t*)(ylp + koff);
            const uint32_t ylB = *(const uint32_t*)(ylp + koff + 8);
#pragma unroll
            for (int f = 0; f < 2; f++) {
                afr[f][0] = hmul2u(afr[f][0], ylA);
                afr[f][1] = hmul2u(afr[f][1], ylA);
                afr[f][2] = hmul2u(afr[f][2], ylB);
                afr[f][3] = hmul2u(afr[f][3], ylB);
            }

            uint32_t bfr[8][2];
#pragma unroll
            for (int gp2 = 0; gp2 < 4; gp2++) {
                uint32_t t[4];
                ldm4(t, stb + roB[gp2] + (((uint32_t)(s * 32) + subB) ^ xoB[gp2]));
                bfr[gp2 * 2 + 0][0] = t[0]; bfr[gp2 * 2 + 0][1] = t[1];
                bfr[gp2 * 2 + 1][0] = t[2]; bfr[gp2 * 2 + 1][1] = t[3];
            }
#pragma unroll
            for (int f = 0; f < 2; f++)
#pragma unroll
                for (int g = 0; g < 8; g++)
                    mma16816(acc[f][g], afr[f], bfr[g]);
        }
    }

    // ---- epilogue: partial tile -> g_s[ks] ----
    float* dst = &g_s[ks][b][ych][0];
    const int cb  = warp_n * 64 + (lane & 3) * 2;
    const int rlo = lane >> 2;
#pragma unroll
    for (int f = 0; f < 2; f++) {
        const int rowb = warp_m * 32 + f * 16 + rlo;
#pragma unroll
        for (int g = 0; g < 8; g++) {
            const int cc2 = cb + g * 8;
            *(float2*)(dst + (size_t)rowb * GR + cc2)       = make_float2(acc[f][g][0], acc[f][g][1]);
            *(float2*)(dst + (size_t)(rowb + 8) * GR + cc2) = make_float2(acc[f][g][2], acc[f][g][3]);
        }
    }
#if __CUDA_ARCH__ >= 900
    cudaTriggerProgrammaticLaunchCompletion();
#endif
}

// =====================  combine / normalize (R7 winner + PDL)  =====================
__global__ void __launch_bounds__(256)
rbf_comb(float* __restrict__ out)
{
    const int bx = blockIdx.x;
    const int b  = bx / 144;
    const int rr = bx % 144;
    const int ch = rr >> 4;
    const int m4 = (((rr & 15) << 8) + threadIdx.x) * 4;

#if __CUDA_ARCH__ >= 900
    cudaGridDependencySynchronize();   // wait for gemm's partials
#endif

    float4 dv = *(const float4*)&g_s[0][b][0][m4];
#pragma unroll
    for (int p = 1; p < KSPL; p++) {
        const float4 d = *(const float4*)&g_s[p][b][0][m4];
        dv.x += d.x; dv.y += d.y; dv.z += d.z; dv.w += d.w;
    }

    float* op = out + ((size_t)b * (YD + 1) + ch) * MM + m4;
    if (ch == 0) {
        *(float4*)op = dv;
        return;
    }
    float4 a = *(const float4*)&g_s[0][b][ch][m4];
#pragma unroll
    for (int p = 1; p < KSPL; p++) {
        const float4 d = *(const float4*)&g_s[p][b][ch][m4];
        a.x += d.x; a.y += d.y; a.z += d.z; a.w += d.w;
    }
    a.x *= rcpf(dv.x + 1e-5f);
    a.y *= rcpf(dv.y + 1e-5f);
    a.z *= rcpf(dv.z + 1e-5f);
    a.w *= rcpf(dv.w + 1e-5f);
    *(float4*)op = a;
}

extern "C" void kernel_launch(void* const* d_in, const int* in_sizes, int n_in,
                              void* d_out, int out_size)
{
    const float* xc    = (const float*)d_in[0];  // (8, 2048, 2)
    const float* yc    = (const float*)d_in[1];  // (8, 2048, 8)
    const float* gp    = (const float*)d_in[2];  // (1, 16384, 2)
    const float* sigma = (const float*)d_in[3];  // scalar
    float* out = (float*)d_out;                  // (8, 9, 128, 128)

    cudaFuncSetAttribute(rbf_gemm, cudaFuncAttributeMaxDynamicSharedMemorySize,
                         NSTAGE * STAGE);

    pre_all<<<400, 256>>>(xc, yc, gp, sigma);

    // gemm: PDL — launch overlaps pre_all's tail
    {
        cudaLaunchConfig_t cfg = {};
        cfg.gridDim = dim3(288, 1, 1);
        cfg.blockDim = dim3(256, 1, 1);
        cfg.dynamicSmemBytes = NSTAGE * STAGE;
        cfg.stream = 0;
        cudaLaunchAttribute attr[1];
        attr[0].id = cudaLaunchAttributeProgrammaticStreamSerialization;
        attr[0].val.programmaticStreamSerializationAllowed = 1;
        cfg.attrs = attr;
        cfg.numAttrs = 1;
        cudaLaunchKernelEx(&cfg, rbf_gemm);
    }

    // comb: PDL — launch overlaps gemm's tail
    {
        cudaLaunchConfig_t cfg = {};
        cfg.gridDim = dim3(1152, 1, 1);
        cfg.blockDim = dim3(256, 1, 1);
        cfg.dynamicSmemBytes = 0;
        cfg.stream = 0;
        cudaLaunchAttribute attr[1];
        attr[0].id = cudaLaunchAttributeProgrammaticStreamSerialization;
        attr[0].val.programmaticStreamSerializationAllowed = 1;
        cfg.attrs = attr;
        cfg.numAttrs = 1;
        cudaLaunchKernelEx(&cfg, rbf_comb, out);
    }
}

// round 15
// speedup vs baseline: 1.3631x; 1.0022x over previous
#include <cuda_runtime.h>
#include <cuda_fp16.h>
#include <cstdint>

#define BB 8
#define NC 2048
#define YD 8
#define GR 128
#define MM (GR*GR)
#define KC 64            // K per chunk (64 halfs = 128B rows)
#define KSPL 4           // K split across CTAs
#define KPER (NC/KSPL)   // 512
#define NCHK (KPER/KC)   // 8 chunks per CTA
#define STAGE 32768      // A(16KB) + B(16KB) per pipeline stage
#define NSTAGE 3

// ---- device scratch ----
__device__ __half g_w[2][BB][GR][NC];        // [axis(0=x,1=y)][b][row][n]
__device__ __half g_yl[BB][YD + 1][NC];      // [b][ych][n], ych 0 -> 1.0
__device__ float  g_s[KSPL][BB][YD + 1][MM]; // partial GEMM outputs

// ---- helpers ----
__device__ __forceinline__ float ex2f(float x) {
    float y; asm("ex2.approx.f32 %0, %1;" : "=f"(y) : "f"(x)); return y;
}
__device__ __forceinline__ float rcpf(float x) {
    float y; asm("rcp.approx.f32 %0, %1;" : "=f"(y) : "f"(x)); return y;
}
__device__ __forceinline__ uint32_t s2u(const void* p) {
    uint32_t a;
    asm("{ .reg .u64 t; cvta.to.shared.u64 t, %1; cvt.u32.u64 %0, t; }" : "=r"(a) : "l"(p));
    return a;
}
__device__ __forceinline__ uint32_t hmul2u(uint32_t a, uint32_t b) {
    __half2 r = __hmul2(*(__half2*)&a, *(__half2*)&b);
    return *(uint32_t*)&r;
}
__device__ __forceinline__ uint32_t pkh2(float hi, float lo) {
    uint32_t r;
    asm("cvt.rn.f16x2.f32 %0, %1, %2;" : "=r"(r) : "f"(hi), "f"(lo));
    return r;
}
__device__ __forceinline__ void cpasync16(uint32_t dst, const void* src) {
    asm volatile("cp.async.cg.shared.global [%0], [%1], 16;" :: "r"(dst), "l"(src) : "memory");
}
#define CP_COMMIT() asm volatile("cp.async.commit_group;" ::: "memory")
#define CP_WAIT1()  asm volatile("cp.async.wait_group 1;" ::: "memory")
#define CP_WAIT0()  asm volatile("cp.async.wait_group 0;" ::: "memory")

__device__ __forceinline__ void ldm4(uint32_t* r, uint32_t addr) {
    asm volatile("ldmatrix.sync.aligned.m8n8.x4.shared.b16 {%0,%1,%2,%3}, [%4];"
        : "=r"(r[0]), "=r"(r[1]), "=r"(r[2]), "=r"(r[3]) : "r"(addr));
}
__device__ __forceinline__ void mma16816(float* d, const uint32_t* a, const uint32_t* bf) {
    asm volatile("mma.sync.aligned.m16n8k16.row.col.f32.f16.f16.f32 "
        "{%0,%1,%2,%3}, {%4,%5,%6,%7}, {%8,%9}, {%0,%1,%2,%3};"
        : "+f"(d[0]), "+f"(d[1]), "+f"(d[2]), "+f"(d[3])
        : "r"(a[0]), "r"(a[1]), "r"(a[2]), "r"(a[3]), "r"(bf[0]), "r"(bf[1]));
}

// =====================  precompute: Gaussian row recurrence (5 ex2/thread)  =====================
// Uniform grid: w[r+1] = w[r]*t[r], t[r+1] = t[r]*r2, r2 = exp2(2*cc*h^2).
// grid = 400: [0,256) weights: axis(2) x b(8) x rowchunk(4 of 32) x nslice(4 of 512)
//             [256,400) yl: b(8) x ych(9) x ns(2)
__global__ void __launch_bounds__(256)
pre_all(const float* __restrict__ xc, const float* __restrict__ yc,
        const float* __restrict__ gp, const float* __restrict__ sigma)
{
    const int bx = blockIdx.x;
    if (bx < 256) {
        const int axis = bx >> 7;
        const int b    = (bx >> 4) & 7;
        const int rc   = (bx >> 2) & 3;      // row chunk of 32
        const int ns   = bx & 3;             // n slice of 512
        const float sg = sigma[0];
        const float cc = -0.5f * 1.4426950408889634f / (sg * sg);

        const int rbase = rc * 32;
        // chunk anchor grid coord + uniform step (broadcast loads)
        const float g0 = axis ? gp[2 * (rbase * GR) + 1] : gp[2 * rbase];
        const float g1 = axis ? gp[2 * ((rbase + 1) * GR) + 1] : gp[2 * (rbase + 1)];
        const float h  = g1 - g0;
        const float u  = cc * h;
        const float r2 = ex2f(2.0f * u * h);

        const int n0 = ns * 512 + threadIdx.x * 2;
        const float4 xv = ((const float4*)xc)[((size_t)b * NC + n0) >> 1];
        const float c0 = axis ? xv.y : xv.x;
        const float c1 = axis ? xv.w : xv.z;

        const float d0 = c0 - g0, d1 = c1 - g0;
        float w0 = ex2f(cc * d0 * d0);
        float w1 = ex2f(cc * d1 * d1);
        float t0 = ex2f(u * (h - 2.0f * d0));
        float t1 = ex2f(u * (h - 2.0f * d1));

        __half* wbase = &g_w[axis][b][rbase][n0];
#pragma unroll 8
        for (int r = 0; r < 32; r++) {
            *(uint32_t*)(wbase + (size_t)r * NC) = pkh2(w1, w0);
            w0 *= t0;  w1 *= t1;
            t0 *= r2;  t1 *= r2;
        }
    } else {
        const int r   = bx - 256;        // 144 = 8 * 9 * 2
        const int b   = r / 18;
        const int rr  = r % 18;
        const int ych = rr >> 1;
        const int ns  = rr & 1;
        const int n0  = ns * 1024 + threadIdx.x * 4;
        uint2 v;
        if (ych == 0) {
            v.x = 0x3C003C00u; v.y = 0x3C003C00u;
        } else {
            const float* yb = yc + ((size_t)b * NC + n0) * YD + (ych - 1);
            v.x = pkh2(yb[8],  yb[0]);
            v.y = pkh2(yb[24], yb[16]);
        }
        *(uint2*)&g_yl[b][ych][n0] = v;
    }
#if __CUDA_ARCH__ >= 900
    cudaTriggerProgrammaticLaunchCompletion();
#endif
}

// =====================  main GEMM: 128x128 tile, cp.async 3-stage (R7 winner)  =====================
// CTA = (b, ych, ks). D[iy 0..127][ix 0..127] = sum_{n in Kslice} (yl[n]*wy[n,iy])*wx[n,ix]
__global__ void __launch_bounds__(256, 2)
rbf_gemm()
{
    extern __shared__ __align__(1024) char smem[];
    const uint32_t sb = s2u(smem);

    const int tid  = threadIdx.x;
    const int wid  = tid >> 5;
    const int lane = tid & 31;
    const int warp_m = wid >> 1;     // 0..3 (m32 each)
    const int warp_n = wid & 1;      // 0..1 (n64 each)

    const int bx  = blockIdx.x;      // 288 = 8 * 9 * 4
    const int b   = bx / 36;
    const int r   = bx % 36;
    const int ych = r >> 2;
    const int ks  = r & 3;

    // ---- cp.async staging maps (per thread: 4 A rows + 4 B rows, 16B each) ----
    const int col8 = tid & 7;
    const int row0 = tid >> 3;       // 0..31
    uint32_t sw[4];
#pragma unroll
    for (int rr = 0; rr < 4; rr++) {
        const uint32_t off = (uint32_t)(row0 + 32 * rr) * 128u + (uint32_t)col8 * 16u;
        sw[rr] = off ^ ((off >> 3) & 0x70);
    }
    const char* aR[4];
    const char* bR[4];
#pragma unroll
    for (int rr = 0; rr < 4; rr++) {
        aR[rr] = (const char*)&g_w[1][b][row0 + 32 * rr][ks * KPER + col8 * 8];
        bR[rr] = (const char*)&g_w[0][b][row0 + 32 * rr][ks * KPER + col8 * 8];
    }

    auto cp_stage = [&](int c, int st) {
        const uint32_t base = sb + (uint32_t)st * STAGE;
        const int boff = c * 128;    // 64 halfs per chunk
#pragma unroll
        for (int rr = 0; rr < 4; rr++) cpasync16(base + sw[rr], aR[rr] + boff);
#pragma unroll
        for (int rr = 0; rr < 4; rr++) cpasync16(base + 16384u + sw[rr], bR[rr] + boff);
    };

    // ---- ldmatrix address components (stage-relative) ----
    uint32_t roA[2], xoA[2];
#pragma unroll
    for (int f = 0; f < 2; f++) {
        const uint32_t rA = warp_m * 32 + f * 16 + (lane & 15);
        roA[f] = rA * 128u;
        xoA[f] = (rA & 7) << 4;
    }
    const uint32_t subA = ((lane >> 4) & 1) * 16u;
    uint32_t roB[4], xoB[4];
#pragma unroll
    for (int gp2 = 0; gp2 < 4; gp2++) {
        const uint32_t rB = warp_n * 64 + gp2 * 16 + ((lane >> 4) & 1) * 8 + (lane & 7);
        roB[gp2] = 16384u + rB * 128u;
        xoB[gp2] = (rB & 7) << 4;
    }
    const uint32_t subB = ((lane >> 3) & 1) * 16u;

    const __half* __restrict__ ylp = &g_yl[b][ych][ks * KPER];
    const uint32_t ylo = (lane & 3) * 2;

    float acc[2][8][4];
#pragma unroll
    for (int f = 0; f < 2; f++)
#pragma unroll
        for (int g = 0; g < 8; g++)
#pragma unroll
            for (int e = 0; e < 4; e++) acc[f][g][e] = 0.0f;

#if __CUDA_ARCH__ >= 900
    cudaGridDependencySynchronize();   // wait for pre_all's writes; prologue above overlapped
#endif

    // ---- 3-stage pipeline prologue ----
    cp_stage(0, 0); CP_COMMIT();
    cp_stage(1, 1); CP_COMMIT();

    for (int k = 0; k < NCHK; k++) {
        if (k == NCHK - 1) { CP_WAIT0(); } else { CP_WAIT1(); }
        __syncthreads();                       // chunk k visible; stage (k+2)%3 free
        if (k + 2 < NCHK) { cp_stage(k + 2, (k + 2) % 3); CP_COMMIT(); }

        const uint32_t stb = sb + (uint32_t)(k % 3) * STAGE;
#pragma unroll
        for (int s = 0; s < 4; s++) {
            uint32_t afr[2][4];
#pragma unroll
            for (int f = 0; f < 2; f++)
                ldm4(afr[f], stb + roA[f] + (((uint32_t)(s * 32) + subA) ^ xoA[f]));

            // yl multiply on A fragments (regs 0,1 = k-lo pair; 2,3 = k-hi pair)
            const uint32_t koff = (uint32_t)(k * KC + s * 16) + ylo;
            const uint32_t ylA = *(const uint32_t*)(ylp + koff);
            const uint32_t ylB = *(const uint32_t*)(ylp + koff + 8);
#pragma unroll
            for (int f = 0; f < 2; f++) {
                afr[f][0] = hmul2u(afr[f][0], ylA);
                afr[f][1] = hmul2u(afr[f][1], ylA);
                afr[f][2] = hmul2u(afr[f][2], ylB);
                afr[f][3] = hmul2u(afr[f][3], ylB);
            }

            uint32_t bfr[8][2];
#pragma unroll
            for (int gp2 = 0; gp2 < 4; gp2++) {
                uint32_t t[4];
                ldm4(t, stb + roB[gp2] + (((uint32_t)(s * 32) + subB) ^ xoB[gp2]));
                bfr[gp2 * 2 + 0][0] = t[0]; bfr[gp2 * 2 + 0][1] = t[1];
                bfr[gp2 * 2 + 1][0] = t[2]; bfr[gp2 * 2 + 1][1] = t[3];
            }
#pragma unroll
            for (int f = 0; f < 2; f++)
#pragma unroll
                for (int g = 0; g < 8; g++)
                    mma16816(acc[f][g], afr[f], bfr[g]);
        }
    }

    // ---- epilogue: partial tile -> g_s[ks] ----
    float* dst = &g_s[ks][b][ych][0];
    const int cb  = warp_n * 64 + (lane & 3) * 2;
    const int rlo = lane >> 2;
#pragma unroll
    for (int f = 0; f < 2; f++) {
        const int rowb = warp_m * 32 + f * 16 + rlo;
#pragma unroll
        for (int g = 0; g < 8; g++) {
            const int cc2 = cb + g * 8;
            *(float2*)(dst + (size_t)rowb * GR + cc2)       = make_float2(acc[f][g][0], acc[f][g][1]);
            *(float2*)(dst + (size_t)(rowb + 8) * GR + cc2) = make_float2(acc[f][g][2], acc[f][g][3]);
        }
    }
#if __CUDA_ARCH__ >= 900
    cudaTriggerProgrammaticLaunchCompletion();
#endif
}

// =====================  combine / normalize (R7 winner + PDL)  =====================
__global__ void __launch_bounds__(256)
rbf_comb(float* __restrict__ out)
{
    const int bx = blockIdx.x;
    const int b  = bx / 144;
    const int rr = bx % 144;
    const int ch = rr >> 4;
    const int m4 = (((rr & 15) << 8) + threadIdx.x) * 4;

#if __CUDA_ARCH__ >= 900
    cudaGridDependencySynchronize();   // wait for gemm's partials
#endif

    float4 dv = *(const float4*)&g_s[0][b][0][m4];
#pragma unroll
    for (int p = 1; p < KSPL; p++) {
        const float4 d = *(const float4*)&g_s[p][b][0][m4];
        dv.x += d.x; dv.y += d.y; dv.z += d.z; dv.w += d.w;
    }

    float* op = out + ((size_t)b * (YD + 1) + ch) * MM + m4;
    if (ch == 0) {
        *(float4*)op = dv;
        return;
    }
    float4 a = *(const float4*)&g_s[0][b][ch][m4];
#pragma unroll
    for (int p = 1; p < KSPL; p++) {
        const float4 d = *(const float4*)&g_s[p][b][ch][m4];
        a.x += d.x; a.y += d.y; a.z += d.z; a.w += d.w;
    }
    a.x *= rcpf(dv.x + 1e-5f);
    a.y *= rcpf(dv.y + 1e-5f);
    a.z *= rcpf(dv.z + 1e-5f);
    a.w *= rcpf(dv.w + 1e-5f);
    *(float4*)op = a;
}

extern "C" void kernel_launch(void* const* d_in, const int* in_sizes, int n_in,
                              void* d_out, int out_size)
{
    const float* xc    = (const float*)d_in[0];  // (8, 2048, 2)
    const float* yc    = (const float*)d_in[1];  // (8, 2048, 8)
    const float* gp    = (const float*)d_in[2];  // (1, 16384, 2)
    const float* sigma = (const float*)d_in[3];  // scalar
    float* out = (float*)d_out;                  // (8, 9, 128, 128)

    cudaFuncSetAttribute(rbf_gemm, cudaFuncAttributeMaxDynamicSharedMemorySize,
                         NSTAGE * STAGE);

    pre_all<<<400, 256>>>(xc, yc, gp, sigma);

    // gemm: PDL — launch overlaps pre_all's tail
    {
        cudaLaunchConfig_t cfg = {};
        cfg.gridDim = dim3(288, 1, 1);
        cfg.blockDim = dim3(256, 1, 1);
        cfg.dynamicSmemBytes = NSTAGE * STAGE;
        cfg.stream = 0;
        cudaLaunchAttribute attr[1];
        attr[0].id = cudaLaunchAttributeProgrammaticStreamSerialization;
        attr[0].val.programmaticStreamSerializationAllowed = 1;
        cfg.attrs = attr;
        cfg.numAttrs = 1;
        cudaLaunchKernelEx(&cfg, rbf_gemm);
    }

    // comb: PDL — launch overlaps gemm's tail
    {
        cudaLaunchConfig_t cfg = {};
        cfg.gridDim = dim3(1152, 1, 1);
        cfg.blockDim = dim3(256, 1, 1);
        cfg.dynamicSmemBytes = 0;
        cfg.stream = 0;
        cudaLaunchAttribute attr[1];
        attr[0].id = cudaLaunchAttributeProgrammaticStreamSerialization;
        attr[0].val.programmaticStreamSerializationAllowed = 1;
        cfg.attrs = attr;
        cfg.numAttrs = 1;
        cudaLaunchKernelEx(&cfg, rbf_comb, out);
    }
}

// round 16
// speedup vs baseline: 1.4844x; 1.0889x over previous
#include <cuda_runtime.h>
#include <cuda_fp16.h>
#include <cstdint>

#define BB 8
#define NC 2048
#define YD 8
#define GR 128
#define MM (GR*GR)
#define KC 64            // K per chunk (64 halfs = 128B rows)
#define KSPL 4           // K split across CTAs
#define KPER (NC/KSPL)   // 512
#define NCHK (KPER/KC)   // 8 chunks per CTA
#define STAGE 32768      // A(16KB) + B(16KB) per pipeline stage
#define NSTAGE 3

// ---- device scratch ----
__device__ __half g_w[2][BB][GR][NC];        // [axis(0=x,1=y)][b][row][n]
__device__ __half g_yl[BB][YD + 1][NC];      // [b][ych][n], ych 0 -> 1.0
__device__ float  g_s[KSPL][BB][YD + 1][MM]; // partial GEMM outputs

// ---- helpers ----
__device__ __forceinline__ float ex2f(float x) {
    float y; asm("ex2.approx.f32 %0, %1;" : "=f"(y) : "f"(x)); return y;
}
__device__ __forceinline__ float rcpf(float x) {
    float y; asm("rcp.approx.f32 %0, %1;" : "=f"(y) : "f"(x)); return y;
}
__device__ __forceinline__ uint32_t s2u(const void* p) {
    uint32_t a;
    asm("{ .reg .u64 t; cvta.to.shared.u64 t, %1; cvt.u32.u64 %0, t; }" : "=r"(a) : "l"(p));
    return a;
}
__device__ __forceinline__ uint32_t hmul2u(uint32_t a, uint32_t b) {
    __half2 r = __hmul2(*(__half2*)&a, *(__half2*)&b);
    return *(uint32_t*)&r;
}
__device__ __forceinline__ uint32_t pkh2(float hi, float lo) {
    uint32_t r;
    asm("cvt.rn.f16x2.f32 %0, %1, %2;" : "=r"(r) : "f"(hi), "f"(lo));
    return r;
}
__device__ __forceinline__ void cpasync16(uint32_t dst, const void* src) {
    asm volatile("cp.async.cg.shared.global [%0], [%1], 16;" :: "r"(dst), "l"(src) : "memory");
}
#define CP_COMMIT() asm volatile("cp.async.commit_group;" ::: "memory")
#define CP_WAIT1()  asm volatile("cp.async.wait_group 1;" ::: "memory")
#define CP_WAIT0()  asm volatile("cp.async.wait_group 0;" ::: "memory")

__device__ __forceinline__ void ldm4(uint32_t* r, uint32_t addr) {
    asm volatile("ldmatrix.sync.aligned.m8n8.x4.shared.b16 {%0,%1,%2,%3}, [%4];"
        : "=r"(r[0]), "=r"(r[1]), "=r"(r[2]), "=r"(r[3]) : "r"(addr));
}
__device__ __forceinline__ void mma16816(float* d, const uint32_t* a, const uint32_t* bf) {
    asm volatile("mma.sync.aligned.m16n8k16.row.col.f32.f16.f16.f32 "
        "{%0,%1,%2,%3}, {%4,%5,%6,%7}, {%8,%9}, {%0,%1,%2,%3};"
        : "+f"(d[0]), "+f"(d[1]), "+f"(d[2]), "+f"(d[3])
        : "r"(a[0]), "r"(a[1]), "r"(a[2]), "r"(a[3]), "r"(bf[0]), "r"(bf[1]));
}

// =====================  precompute: Gaussian row recurrence (R15)  =====================
__global__ void __launch_bounds__(256)
pre_all(const float* __restrict__ xc, const float* __restrict__ yc,
        const float* __restrict__ gp, const float* __restrict__ sigma)
{
    const int bx = blockIdx.x;
    if (bx < 256) {
        const int axis = bx >> 7;
        const int b    = (bx >> 4) & 7;
        const int rc   = (bx >> 2) & 3;      // row chunk of 32
        const int ns   = bx & 3;             // n slice of 512
        const float sg = sigma[0];
        const float cc = -0.5f * 1.4426950408889634f / (sg * sg);

        const int rbase = rc * 32;
        const float g0 = axis ? gp[2 * (rbase * GR) + 1] : gp[2 * rbase];
        const float g1 = axis ? gp[2 * ((rbase + 1) * GR) + 1] : gp[2 * (rbase + 1)];
        const float h  = g1 - g0;
        const float u  = cc * h;
        const float r2 = ex2f(2.0f * u * h);

        const int n0 = ns * 512 + threadIdx.x * 2;
        const float4 xv = ((const float4*)xc)[((size_t)b * NC + n0) >> 1];
        const float c0 = axis ? xv.y : xv.x;
        const float c1 = axis ? xv.w : xv.z;

        const float d0 = c0 - g0, d1 = c1 - g0;
        float w0 = ex2f(cc * d0 * d0);
        float w1 = ex2f(cc * d1 * d1);
        float t0 = ex2f(u * (h - 2.0f * d0));
        float t1 = ex2f(u * (h - 2.0f * d1));

        __half* wbase = &g_w[axis][b][rbase][n0];
#pragma unroll 8
        for (int r = 0; r < 32; r++) {
            *(uint32_t*)(wbase + (size_t)r * NC) = pkh2(w1, w0);
            w0 *= t0;  w1 *= t1;
            t0 *= r2;  t1 *= r2;
        }
    } else {
        const int r   = bx - 256;        // 144 = 8 * 9 * 2
        const int b   = r / 18;
        const int rr  = r % 18;
        const int ych = rr >> 1;
        const int ns  = rr & 1;
        const int n0  = ns * 1024 + threadIdx.x * 4;
        uint2 v;
        if (ych == 0) {
            v.x = 0x3C003C00u; v.y = 0x3C003C00u;
        } else {
            const float* yb = yc + ((size_t)b * NC + n0) * YD + (ych - 1);
            v.x = pkh2(yb[8],  yb[0]);
            v.y = pkh2(yb[24], yb[16]);
        }
        *(uint2*)&g_yl[b][ych][n0] = v;
    }
#if __CUDA_ARCH__ >= 900
    cudaTriggerProgrammaticLaunchCompletion();
#endif
}

// =====================  GEMM: 128x128 tile, 4 warps of m64n64, cp.async 3-stage  =====================
// CTA = (b, ych, ks), 128 threads. D[iy][ix] = sum_{Kslice} (yl*wy[n,iy])*wx[n,ix]
__global__ void __launch_bounds__(128, 2)
rbf_gemm()
{
    extern __shared__ __align__(1024) char smem[];
    const uint32_t sb = s2u(smem);

    const int tid  = threadIdx.x;
    const int wid  = tid >> 5;       // 0..3
    const int lane = tid & 31;
    const int warp_m = wid >> 1;     // 0..1 (m64 each)
    const int warp_n = wid & 1;      // 0..1 (n64 each)

    const int bx  = blockIdx.x;      // 288 = 8 * 9 * 4
    const int b   = bx / 36;
    const int r   = bx % 36;
    const int ych = r >> 2;
    const int ks  = r & 3;

    // ---- cp.async staging: thread covers rows {row0+16i}, 16B seg col8 ----
    const uint32_t off0 = (uint32_t)(tid >> 3) * 128u + (uint32_t)(tid & 7) * 16u;
    const uint32_t sw0  = off0 ^ ((off0 >> 3) & 0x70);    // +2048*i preserves swizzle
    const char* aBase = (const char*)&g_w[1][b][tid >> 3][ks * KPER + (tid & 7) * 8];
    const char* bBase = (const char*)&g_w[0][b][tid >> 3][ks * KPER + (tid & 7) * 8];

    auto cp_stage = [&](int c, int st) {
        const uint32_t dst = sb + (uint32_t)st * STAGE + sw0;
        const int boff = c * 128;                 // 64 halfs per chunk
#pragma unroll
        for (int rr = 0; rr < 8; rr++)
            cpasync16(dst + (uint32_t)rr * 2048u, aBase + boff + rr * (16 * NC * 2));
#pragma unroll
        for (int rr = 0; rr < 8; rr++)
            cpasync16(dst + 16384u + (uint32_t)rr * 2048u, bBase + boff + rr * (16 * NC * 2));
    };

    // ---- ldmatrix addressing: single xor, affine row offsets ----
    const uint32_t xo   = (uint32_t)(lane & 7) << 4;
    const uint32_t roA0 = ((uint32_t)(warp_m * 64 + (lane & 15))) * 128u;
    const uint32_t subA = ((lane >> 4) & 1) * 16u;
    const uint32_t roB0 = 16384u
        + ((uint32_t)(warp_n * 64 + ((lane >> 4) & 1) * 8 + (lane & 7))) * 128u;
    const uint32_t subB = ((lane >> 3) & 1) * 16u;

    const __half* __restrict__ ylp = &g_yl[b][ych][ks * KPER] + (lane & 3) * 2;

    float acc[4][8][4];
#pragma unroll
    for (int f = 0; f < 4; f++)
#pragma unroll
        for (int g = 0; g < 8; g++)
#pragma unroll
            for (int e = 0; e < 4; e++) acc[f][g][e] = 0.0f;

#if __CUDA_ARCH__ >= 900
    cudaGridDependencySynchronize();   // wait for pre_all's writes
#endif

    // ---- 3-stage pipeline prologue ----
    cp_stage(0, 0); CP_COMMIT();
    cp_stage(1, 1); CP_COMMIT();

    for (int k = 0; k < NCHK; k++) {
        if (k == NCHK - 1) { CP_WAIT0(); } else { CP_WAIT1(); }
        __syncthreads();                       // chunk k visible; stage (k+2)%3 free
        if (k + 2 < NCHK) { cp_stage(k + 2, (k + 2) % 3); CP_COMMIT(); }

        const uint32_t stb = sb + (uint32_t)(k % 3) * STAGE;
#pragma unroll
        for (int s = 0; s < 4; s++) {
            const uint32_t qA = ((uint32_t)(s * 32) + subA) ^ xo;
            const uint32_t qB = ((uint32_t)(s * 32) + subB) ^ xo;

            // A fragments: m64 -> 4 ldm4; then yl multiply
            uint32_t afr[4][4];
#pragma unroll
            for (int f = 0; f < 4; f++)
                ldm4(afr[f], stb + roA0 + (uint32_t)f * 2048u + qA);

            const __half* ylk = ylp + (uint32_t)(k * KC + s * 16);
            const uint32_t ylA = *(const uint32_t*)(ylk);
            const uint32_t ylB = *(const uint32_t*)(ylk + 8);
#pragma unroll
            for (int f = 0; f < 4; f++) {
                afr[f][0] = hmul2u(afr[f][0], ylA);
                afr[f][1] = hmul2u(afr[f][1], ylA);
                afr[f][2] = hmul2u(afr[f][2], ylB);
                afr[f][3] = hmul2u(afr[f][3], ylB);
            }

            // B fragments: n64 -> 4 ldm4 -> 8 n8 groups
            uint32_t bfr[8][2];
#pragma unroll
            for (int gp2 = 0; gp2 < 4; gp2++) {
                uint32_t t[4];
                ldm4(t, stb + roB0 + (uint32_t)gp2 * 2048u + qB);
                bfr[gp2 * 2 + 0][0] = t[0]; bfr[gp2 * 2 + 0][1] = t[1];
                bfr[gp2 * 2 + 1][0] = t[2]; bfr[gp2 * 2 + 1][1] = t[3];
            }

            // 32 independent MMAs
#pragma unroll
            for (int f = 0; f < 4; f++)
#pragma unroll
                for (int g = 0; g < 8; g++)
                    mma16816(acc[f][g], afr[f], bfr[g]);
        }
    }

    // ---- epilogue: partial tile -> g_s[ks] ----
    float* dst = &g_s[ks][b][ych][0];
    const int cb  = warp_n * 64 + (lane & 3) * 2;
    const int rlo = lane >> 2;
#pragma unroll
    for (int f = 0; f < 4; f++) {
        const int rowb = warp_m * 64 + f * 16 + rlo;
#pragma unroll
        for (int g = 0; g < 8; g++) {
            const int cc2 = cb + g * 8;
            *(float2*)(dst + (size_t)rowb * GR + cc2)       = make_float2(acc[f][g][0], acc[f][g][1]);
            *(float2*)(dst + (size_t)(rowb + 8) * GR + cc2) = make_float2(acc[f][g][2], acc[f][g][3]);
        }
    }
#if __CUDA_ARCH__ >= 900
    cudaTriggerProgrammaticLaunchCompletion();
#endif
}

// =====================  combine / normalize (R7 winner + PDL)  =====================
__global__ void __launch_bounds__(256)
rbf_comb(float* __restrict__ out)
{
    const int bx = blockIdx.x;
    const int b  = bx / 144;
    const int rr = bx % 144;
    const int ch = rr >> 4;
    const int m4 = (((rr & 15) << 8) + threadIdx.x) * 4;

#if __CUDA_ARCH__ >= 900
    cudaGridDependencySynchronize();   // wait for gemm's partials
#endif

    float4 dv = *(const float4*)&g_s[0][b][0][m4];
#pragma unroll
    for (int p = 1; p < KSPL; p++) {
        const float4 d = *(const float4*)&g_s[p][b][0][m4];
        dv.x += d.x; dv.y += d.y; dv.z += d.z; dv.w += d.w;
    }

    float* op = out + ((size_t)b * (YD + 1) + ch) * MM + m4;
    if (ch == 0) {
        *(float4*)op = dv;
        return;
    }
    float4 a = *(const float4*)&g_s[0][b][ch][m4];
#pragma unroll
    for (int p = 1; p < KSPL; p++) {
        const float4 d = *(const float4*)&g_s[p][b][ch][m4];
        a.x += d.x; a.y += d.y; a.z += d.z; a.w += d.w;
    }
    a.x *= rcpf(dv.x + 1e-5f);
    a.y *= rcpf(dv.y + 1e-5f);
    a.z *= rcpf(dv.z + 1e-5f);
    a.w *= rcpf(dv.w + 1e-5f);
    *(float4*)op = a;
}

extern "C" void kernel_launch(void* const* d_in, const int* in_sizes, int n_in,
                              void* d_out, int out_size)
{
    const float* xc    = (const float*)d_in[0];  // (8, 2048, 2)
    const float* yc    = (const float*)d_in[1];  // (8, 2048, 8)
    const float* gp    = (const float*)d_in[2];  // (1, 16384, 2)
    const float* sigma = (const float*)d_in[3];  // scalar
    float* out = (float*)d_out;                  // (8, 9, 128, 128)

    cudaFuncSetAttribute(rbf_gemm, cudaFuncAttributeMaxDynamicSharedMemorySize,
                         NSTAGE * STAGE);

    pre_all<<<400, 256>>>(xc, yc, gp, sigma);

    // gemm: PDL — launch overlaps pre_all's tail
    {
        cudaLaunchConfig_t cfg = {};
        cfg.gridDim = dim3(288, 1, 1);
        cfg.blockDim = dim3(128, 1, 1);
        cfg.dynamicSmemBytes = NSTAGE * STAGE;
        cfg.stream = 0;
        cudaLaunchAttribute attr[1];
        attr[0].id = cudaLaunchAttributeProgrammaticStreamSerialization;
        attr[0].val.programmaticStreamSerializationAllowed = 1;
        cfg.attrs = attr;
        cfg.numAttrs = 1;
        cudaLaunchKernelEx(&cfg, rbf_gemm);
    }

    // comb: PDL — launch overlaps gemm's tail
    {
        cudaLaunchConfig_t cfg = {};
        cfg.gridDim = dim3(1152, 1, 1);
        cfg.blockDim = dim3(256, 1, 1);
        cfg.dynamicSmemBytes = 0;
        cfg.stream = 0;
        cudaLaunchAttribute attr[1];
        attr[0].id = cudaLaunchAttributeProgrammaticStreamSerialization;
        attr[0].val.programmaticStreamSerializationAllowed = 1;
        cfg.attrs = attr;
        cfg.numAttrs = 1;
        cudaLaunchKernelEx(&cfg, rbf_comb, out);
    }
}